// round 1
// baseline (speedup 1.0000x reference)
#include <cuda_runtime.h>

#define NN 1024
#define DD 32
#define HH 64
#define TB 256
#define LN_EPS 1e-5f

// Precomputed hs = X @ W1[:32], hd = X @ W1[32:] + b1
__device__ float g_hs[NN * HH];
__device__ float g_hd[NN * HH];

__global__ void prep_kernel(const float* __restrict__ X,
                            const float* __restrict__ W1,
                            const float* __restrict__ b1) {
    __shared__ float xs[DD];
    int i = blockIdx.x;
    int n = threadIdx.x;  // 64 threads, one output column each
    if (n < DD) xs[n] = X[i * DD + n];
    __syncthreads();
    float hs = 0.f;
    float hd = b1[n];
    #pragma unroll
    for (int d = 0; d < DD; d++) {
        float xv = xs[d];
        hs = fmaf(xv, W1[d * HH + n], hs);
        hd = fmaf(xv, W1[(DD + d) * HH + n], hd);
    }
    g_hs[i * HH + n] = hs;
    g_hd[i * HH + n] = hd;
}

__global__ __launch_bounds__(TB) void pair_kernel(
    const float* __restrict__ g1, const float* __restrict__ be1,
    const float* __restrict__ W2, const float* __restrict__ b2,
    const float* __restrict__ g2, const float* __restrict__ be2,
    const float* __restrict__ W3, const float* __restrict__ b3,
    float* __restrict__ out) {
    extern __shared__ float smem[];
    float* w2s  = smem;               // HH*HH = 4096 floats (16 KB)
    float* vs   = smem + HH * HH;     // HH*TB = 16384 floats (64 KB), layout [k][tid]
    float* pars = vs + HH * TB;       // g1 | be1 | g2 | be2 | w3 | b3

    int tid = threadIdx.x;

    for (int idx = tid; idx < HH * HH; idx += TB) w2s[idx] = W2[idx];
    if (tid < HH) {
        pars[tid]          = g1[tid];
        pars[HH + tid]     = be1[tid];
        pars[2 * HH + tid] = g2[tid];
        pars[3 * HH + tid] = be2[tid];
        pars[4 * HH + tid] = W3[tid];
    }
    if (tid == 0) pars[5 * HH] = b3[0];
    __syncthreads();

    // 16x16 pair tile per CTA, one pair per thread
    int i = (blockIdx.y << 4) + (tid >> 4);
    int j = (blockIdx.x << 4) + (tid & 15);

    // ---- phase 1: x = hs[i] + hd[j]  (b1 folded into hd), LN1 stats ----
    float x[HH];
    const float4* hs4 = reinterpret_cast<const float4*>(g_hs + i * HH);
    const float4* hd4 = reinterpret_cast<const float4*>(g_hd + j * HH);
    float s1 = 0.f, s2 = 0.f;
    #pragma unroll
    for (int q = 0; q < HH / 4; q++) {
        float4 a = hs4[q];
        float4 b = hd4[q];
        float v0 = a.x + b.x, v1 = a.y + b.y, v2 = a.z + b.z, v3 = a.w + b.w;
        x[4 * q + 0] = v0; x[4 * q + 1] = v1;
        x[4 * q + 2] = v2; x[4 * q + 3] = v3;
        s1 += (v0 + v1) + (v2 + v3);
        s2 += (v0 * v0 + v1 * v1) + (v2 * v2 + v3 * v3);
    }
    float mu  = s1 * (1.f / HH);
    float var = s2 * (1.f / HH) - mu * mu;
    float rs  = rsqrtf(var + LN_EPS);
    // v = relu(LN(x)) -> smem transposed [k][tid] (conflict-free per-lane column)
    #pragma unroll
    for (int k = 0; k < HH; k++) {
        float t = fmaf((x[k] - mu) * rs, pars[k], pars[HH + k]);
        vs[k * TB + tid] = fmaxf(t, 0.f);
    }

    // ---- phase 2: u = v @ W2 + b2, u fully in registers ----
    float u[HH];
    #pragma unroll
    for (int q = 0; q < HH / 4; q++) {
        float4 bb = __ldg(reinterpret_cast<const float4*>(b2) + q);
        u[4 * q + 0] = bb.x; u[4 * q + 1] = bb.y;
        u[4 * q + 2] = bb.z; u[4 * q + 3] = bb.w;
    }
    #pragma unroll 4
    for (int k = 0; k < HH; k++) {
        float vk = vs[k * TB + tid];
        const float4* wrow = reinterpret_cast<const float4*>(w2s + k * HH);
        #pragma unroll
        for (int q = 0; q < HH / 4; q++) {
            float4 w = wrow[q];
            u[4 * q + 0] = fmaf(vk, w.x, u[4 * q + 0]);
            u[4 * q + 1] = fmaf(vk, w.y, u[4 * q + 1]);
            u[4 * q + 2] = fmaf(vk, w.z, u[4 * q + 2]);
            u[4 * q + 3] = fmaf(vk, w.w, u[4 * q + 3]);
        }
    }

    // ---- LN2 + relu + dot(W3) + sigmoid ----
    float t1 = 0.f, t2 = 0.f;
    #pragma unroll
    for (int k = 0; k < HH; k++) {
        t1 += u[k];
        t2 = fmaf(u[k], u[k], t2);
    }
    float mu2  = t1 * (1.f / HH);
    float var2 = t2 * (1.f / HH) - mu2 * mu2;
    float rs2  = rsqrtf(var2 + LN_EPS);

    float acc = pars[5 * HH];  // b3
    #pragma unroll
    for (int k = 0; k < HH; k++) {
        float t = fmaf((u[k] - mu2) * rs2, pars[2 * HH + k], pars[3 * HH + k]);
        acc = fmaf(fmaxf(t, 0.f), pars[4 * HH + k], acc);
    }
    out[i * NN + j] = 1.f / (1.f + __expf(-acc));
}

extern "C" void kernel_launch(void* const* d_in, const int* in_sizes, int n_in,
                              void* d_out, int out_size) {
    const float* X   = (const float*)d_in[0];
    const float* W1  = (const float*)d_in[1];
    const float* b1  = (const float*)d_in[2];
    const float* g1  = (const float*)d_in[3];
    const float* be1 = (const float*)d_in[4];
    const float* W2  = (const float*)d_in[5];
    const float* b2  = (const float*)d_in[6];
    const float* g2  = (const float*)d_in[7];
    const float* be2 = (const float*)d_in[8];
    const float* W3  = (const float*)d_in[9];
    const float* b3  = (const float*)d_in[10];
    float* out = (float*)d_out;

    size_t shmem = (size_t)(HH * HH + HH * TB + 5 * HH + 1) * sizeof(float);
    cudaFuncSetAttribute(pair_kernel, cudaFuncAttributeMaxDynamicSharedMemorySize,
                         (int)shmem);

    prep_kernel<<<NN, HH>>>(X, W1, b1);
    dim3 grid(NN / 16, NN / 16);
    pair_kernel<<<grid, TB, shmem>>>(g1, be1, W2, b2, g2, be2, W3, b3, out);
}

// round 3
// speedup vs baseline: 3.1939x; 3.1939x over previous
#include <cuda_runtime.h>
#include <cuda_bf16.h>
#include <cstdint>

#define NN 1024
#define DD 32
#define HH 64
#define LN_EPS 1e-5f

// ---------------- device globals ----------------
__device__ float g_hs[NN * HH];            // X @ W1[:32]
__device__ float g_hd[NN * HH];            // X @ W1[32:] + b1
__device__ uint4 g_w2f[8 * 4 * 32];        // W2 in mma B-frag layout: [nt][kk][lane] = {bhi0,bhi1,blo0,blo1}

// ---------------- helpers ----------------
__device__ __forceinline__ uint32_t pack_bf16x2(float lo, float hi) {
    __nv_bfloat162 t = __floats2bfloat162_rn(lo, hi);
    return *reinterpret_cast<uint32_t*>(&t);
}
__device__ __forceinline__ float bf_hi(float v) {
    return __bfloat162float(__float2bfloat16(v));
}
__device__ __forceinline__ void mma_bf16(float* c, uint32_t a0, uint32_t a1,
                                         uint32_t a2, uint32_t a3,
                                         uint32_t b0, uint32_t b1) {
    asm volatile(
        "mma.sync.aligned.m16n8k16.row.col.f32.bf16.bf16.f32 "
        "{%0,%1,%2,%3}, {%4,%5,%6,%7}, {%8,%9}, {%0,%1,%2,%3};"
        : "+f"(c[0]), "+f"(c[1]), "+f"(c[2]), "+f"(c[3])
        : "r"(a0), "r"(a1), "r"(a2), "r"(a3), "r"(b0), "r"(b1));
}
__device__ __forceinline__ float qred(float v) {
    v += __shfl_xor_sync(0xffffffffu, v, 1);
    v += __shfl_xor_sync(0xffffffffu, v, 2);
    return v;
}

// ---------------- prep kernels ----------------
__global__ void prep_kernel(const float* __restrict__ X,
                            const float* __restrict__ W1,
                            const float* __restrict__ b1) {
    __shared__ float xs[DD];
    int i = blockIdx.x;
    int n = threadIdx.x;
    if (n < DD) xs[n] = X[i * DD + n];
    __syncthreads();
    float hs = 0.f, hd = b1[n];
    #pragma unroll
    for (int d = 0; d < DD; d++) {
        float xv = xs[d];
        hs = fmaf(xv, W1[d * HH + n], hs);
        hd = fmaf(xv, W1[(DD + d) * HH + n], hd);
    }
    g_hs[i * HH + n] = hs;
    g_hd[i * HH + n] = hd;
}

// W2 -> mma.m16n8k16 B-fragment image, split bf16 hi/lo.
// B[k][n] = W2[k][n]. Frag for (nt, kk, lane):
//   n = nt*8 + lane/4, kq = kk*16 + (lane%4)*2
//   b0 = {B[kq][n], B[kq+1][n]}, b1 = {B[kq+8][n], B[kq+9][n]}
__global__ void prep_w2f(const float* __restrict__ W2) {
    int t = blockIdx.x * 256 + threadIdx.x;   // 1024 entries
    int lane = t & 31;
    int kk = (t >> 5) & 3;
    int nt = t >> 7;
    int n  = nt * 8 + (lane >> 2);
    int kq = kk * 16 + (lane & 3) * 2;
    float w00 = W2[kq * HH + n],       w01 = W2[(kq + 1) * HH + n];
    float w10 = W2[(kq + 8) * HH + n], w11 = W2[(kq + 9) * HH + n];
    float h00 = bf_hi(w00), h01 = bf_hi(w01), h10 = bf_hi(w10), h11 = bf_hi(w11);
    uint4 r;
    r.x = pack_bf16x2(h00, h01);
    r.y = pack_bf16x2(h10, h11);
    r.z = pack_bf16x2(w00 - h00, w01 - h01);
    r.w = pack_bf16x2(w10 - h10, w11 - h11);
    g_w2f[t] = r;
}

// ---------------- main pair kernel ----------------
// CTA: 128 threads (4 warps), tile = 8 i x 16 j = 128 pairs.
// Warp w covers i in {by*8 + 2w, +1}; each mtile = one i x 16 j (rows = j).
__global__ __launch_bounds__(128) void pair_kernel(
    const float* __restrict__ g1, const float* __restrict__ be1,
    const float* __restrict__ b2, const float* __restrict__ g2,
    const float* __restrict__ be2, const float* __restrict__ W3,
    const float* __restrict__ b3, float* __restrict__ out) {
    __shared__ uint4 s_bf[8 * 4 * 32];   // 16 KB B fragments
    __shared__ float s_g1[HH], s_be1[HH], s_b2[HH], s_g2[HH], s_be2[HH], s_w3[HH];
    __shared__ float s_b3;

    int tid = threadIdx.x;
    int w = tid >> 5, lane = tid & 31;
    int qr = lane >> 2, qc = lane & 3;

    #pragma unroll
    for (int idx = tid; idx < 1024; idx += 128) s_bf[idx] = g_w2f[idx];
    if (tid < HH) {
        s_g1[tid]  = g1[tid];
        s_be1[tid] = be1[tid];
        s_b2[tid]  = b2[tid];
        s_g2[tid]  = g2[tid];
        s_be2[tid] = be2[tid];
        s_w3[tid]  = W3[tid];
    }
    if (tid == 0) s_b3 = b3[0];
    __syncthreads();

    int bx = blockIdx.x, by = blockIdx.y;

    #pragma unroll
    for (int mt = 0; mt < 2; mt++) {
        int i  = by * 8 + w * 2 + mt;
        int j1 = bx * 16 + qr;            // row r of mtile
        // j2 = j1 + 8 (row r+8)

        const float2* hsp = reinterpret_cast<const float2*>(g_hs + i * HH);
        const float2* hd1 = reinterpret_cast<const float2*>(g_hd + j1 * HH);
        const float2* hd2 = reinterpret_cast<const float2*>(g_hd + (j1 + 8) * HH);

        // ---- x = hs[i] + hd[j] at this lane's 16 fragment columns ----
        float x1[16], x2[16];
        float s11 = 0.f, s12 = 0.f, s21 = 0.f, s22 = 0.f;
        #pragma unroll
        for (int kk = 0; kk < 4; kk++) {
            #pragma unroll
            for (int h = 0; h < 2; h++) {
                int c2 = (kk * 16 + h * 8 + qc * 2) >> 1;   // float2 index
                float2 a  = hsp[c2];
                float2 d1 = hd1[c2];
                float2 d2 = hd2[c2];
                int o = kk * 4 + h * 2;
                float v1a = a.x + d1.x, v1b = a.y + d1.y;
                float v2a = a.x + d2.x, v2b = a.y + d2.y;
                x1[o] = v1a; x1[o + 1] = v1b;
                x2[o] = v2a; x2[o + 1] = v2b;
                s11 += v1a + v1b; s12 += v1a * v1a + v1b * v1b;
                s21 += v2a + v2b; s22 += v2a * v2a + v2b * v2b;
            }
        }
        s11 = qred(s11); s12 = qred(s12);
        s21 = qred(s21); s22 = qred(s22);
        float mu1 = s11 * (1.f / HH);
        float rs1 = rsqrtf(s12 * (1.f / HH) - mu1 * mu1 + LN_EPS);
        float mu2 = s21 * (1.f / HH);
        float rs2 = rsqrtf(s22 * (1.f / HH) - mu2 * mu2 + LN_EPS);

        // ---- v = relu(LN1(x)), split bf16 hi/lo, packed in A-frag layout ----
        uint32_t ahi[4][4], alo[4][4];
        #pragma unroll
        for (int kk = 0; kk < 4; kk++) {
            #pragma unroll
            for (int h = 0; h < 2; h++) {
                int c = kk * 16 + h * 8 + qc * 2;
                int o = kk * 4 + h * 2;
                float2 g1c  = *reinterpret_cast<const float2*>(s_g1 + c);
                float2 be1c = *reinterpret_cast<const float2*>(s_be1 + c);
                float v1a = fmaxf(fmaf((x1[o]     - mu1) * rs1, g1c.x, be1c.x), 0.f);
                float v1b = fmaxf(fmaf((x1[o + 1] - mu1) * rs1, g1c.y, be1c.y), 0.f);
                float v2a = fmaxf(fmaf((x2[o]     - mu2) * rs2, g1c.x, be1c.x), 0.f);
                float v2b = fmaxf(fmaf((x2[o + 1] - mu2) * rs2, g1c.y, be1c.y), 0.f);
                float h1a = bf_hi(v1a), h1b = bf_hi(v1b);
                float h2a = bf_hi(v2a), h2b = bf_hi(v2b);
                int ri = h * 2;
                ahi[kk][ri]     = pack_bf16x2(h1a, h1b);          // a0/a2: row r
                ahi[kk][ri + 1] = pack_bf16x2(h2a, h2b);          // a1/a3: row r+8
                alo[kk][ri]     = pack_bf16x2(v1a - h1a, v1b - h1b);
                alo[kk][ri + 1] = pack_bf16x2(v2a - h2a, v2b - h2b);
            }
        }

        // ---- u = v @ W2 via 3-pass split-bf16 mma ----
        float acc[8][4];
        #pragma unroll
        for (int nt = 0; nt < 8; nt++)
            #pragma unroll
            for (int e = 0; e < 4; e++) acc[nt][e] = 0.f;
        #pragma unroll
        for (int nt = 0; nt < 8; nt++) {
            #pragma unroll
            for (int kk = 0; kk < 4; kk++) {
                uint4 B = s_bf[(nt * 4 + kk) * 32 + lane];
                mma_bf16(acc[nt], ahi[kk][0], ahi[kk][1], ahi[kk][2], ahi[kk][3], B.x, B.y); // hi*hi
                mma_bf16(acc[nt], ahi[kk][0], ahi[kk][1], ahi[kk][2], ahi[kk][3], B.z, B.w); // hi*lo
                mma_bf16(acc[nt], alo[kk][0], alo[kk][1], alo[kk][2], alo[kk][3], B.x, B.y); // lo*hi
            }
        }

        // ---- epilogue: +b2, LN2, relu, dot(W3), sigmoid ----
        float u1[16], u2[16];
        float t11 = 0.f, t12 = 0.f, t21 = 0.f, t22 = 0.f;
        #pragma unroll
        for (int nt = 0; nt < 8; nt++) {
            int c = nt * 8 + qc * 2;
            float2 b2c = *reinterpret_cast<const float2*>(s_b2 + c);
            float va = acc[nt][0] + b2c.x, vb = acc[nt][1] + b2c.y;
            float wa = acc[nt][2] + b2c.x, wb = acc[nt][3] + b2c.y;
            u1[nt * 2] = va; u1[nt * 2 + 1] = vb;
            u2[nt * 2] = wa; u2[nt * 2 + 1] = wb;
            t11 += va + vb; t12 += va * va + vb * vb;
            t21 += wa + wb; t22 += wa * wa + wb * wb;
        }
        t11 = qred(t11); t12 = qred(t12);
        t21 = qred(t21); t22 = qred(t22);
        float m1 = t11 * (1.f / HH);
        float r1 = rsqrtf(t12 * (1.f / HH) - m1 * m1 + LN_EPS);
        float m2 = t21 * (1.f / HH);
        float r2 = rsqrtf(t22 * (1.f / HH) - m2 * m2 + LN_EPS);

        float d1 = 0.f, d2 = 0.f;
        #pragma unroll
        for (int nt = 0; nt < 8; nt++) {
            int c = nt * 8 + qc * 2;
            float2 g2c  = *reinterpret_cast<const float2*>(s_g2 + c);
            float2 be2c = *reinterpret_cast<const float2*>(s_be2 + c);
            float2 w3c  = *reinterpret_cast<const float2*>(s_w3 + c);
            float z;
            z = fmaxf(fmaf((u1[nt * 2]     - m1) * r1, g2c.x, be2c.x), 0.f); d1 = fmaf(z, w3c.x, d1);
            z = fmaxf(fmaf((u1[nt * 2 + 1] - m1) * r1, g2c.y, be2c.y), 0.f); d1 = fmaf(z, w3c.y, d1);
            z = fmaxf(fmaf((u2[nt * 2]     - m2) * r2, g2c.x, be2c.x), 0.f); d2 = fmaf(z, w3c.x, d2);
            z = fmaxf(fmaf((u2[nt * 2 + 1] - m2) * r2, g2c.y, be2c.y), 0.f); d2 = fmaf(z, w3c.y, d2);
        }
        d1 = qred(d1); d2 = qred(d2);
        if (qc == 0) {
            float o1 = 1.f / (1.f + __expf(-(d1 + s_b3)));
            float o2 = 1.f / (1.f + __expf(-(d2 + s_b3)));
            out[i * NN + j1]     = o1;
            out[i * NN + j1 + 8] = o2;
        }
    }
}

// ---------------- launch ----------------
extern "C" void kernel_launch(void* const* d_in, const int* in_sizes, int n_in,
                              void* d_out, int out_size) {
    const float* X   = (const float*)d_in[0];
    const float* W1  = (const float*)d_in[1];
    const float* b1  = (const float*)d_in[2];
    const float* g1  = (const float*)d_in[3];
    const float* be1 = (const float*)d_in[4];
    const float* W2  = (const float*)d_in[5];
    const float* b2  = (const float*)d_in[6];
    const float* g2  = (const float*)d_in[7];
    const float* be2 = (const float*)d_in[8];
    const float* W3  = (const float*)d_in[9];
    const float* b3  = (const float*)d_in[10];
    float* out = (float*)d_out;

    prep_kernel<<<NN, HH>>>(X, W1, b1);
    prep_w2f<<<4, 256>>>(W2);
    dim3 grid(NN / 16, NN / 8);
    pair_kernel<<<grid, 128>>>(g1, be1, b2, g2, be2, W3, b3, out);
}

// round 4
// speedup vs baseline: 3.5618x; 1.1152x over previous
#include <cuda_runtime.h>
#include <cuda_fp16.h>
#include <cstdint>

#define NN 1024
#define DD 32
#define HH 64
#define LN_EPS 1e-5f

// ---------------- device globals ----------------
__device__ float g_hs[NN * HH];            // X @ W1[:32]
__device__ float g_hd[NN * HH];            // X @ W1[32:] + b1
__device__ uint4 g_w2f[8 * 4 * 32];        // W2 in mma B-frag layout: [nt][kk][lane] = {wh0,wh1,wl0,wl1} (fp16)

// ---------------- helpers ----------------
__device__ __forceinline__ uint32_t pack_h2(float a, float b) {
    __half2 t = __floats2half2_rn(a, b);
    return *reinterpret_cast<uint32_t*>(&t);
}
__device__ __forceinline__ float h_hi(float v) {
    return __half2float(__float2half_rn(v));
}
__device__ __forceinline__ void mma_f16(float* c, uint32_t a0, uint32_t a1,
                                        uint32_t a2, uint32_t a3,
                                        uint32_t b0, uint32_t b1) {
    asm volatile(
        "mma.sync.aligned.m16n8k16.row.col.f32.f16.f16.f32 "
        "{%0,%1,%2,%3}, {%4,%5,%6,%7}, {%8,%9}, {%0,%1,%2,%3};"
        : "+f"(c[0]), "+f"(c[1]), "+f"(c[2]), "+f"(c[3])
        : "r"(a0), "r"(a1), "r"(a2), "r"(a3), "r"(b0), "r"(b1));
}
__device__ __forceinline__ float qred(float v) {
    v += __shfl_xor_sync(0xffffffffu, v, 1);
    v += __shfl_xor_sync(0xffffffffu, v, 2);
    return v;
}

// ---------------- merged prep kernel ----------------
// Blocks [0,256): hs/hd for 4 i-rows each (256 thr). Blocks [256,260): W2 frag split.
__global__ void prep_all(const float* __restrict__ X,
                         const float* __restrict__ W1,
                         const float* __restrict__ b1,
                         const float* __restrict__ W2) {
    if (blockIdx.x < 256) {
        __shared__ float xs[4][DD];
        int sub = threadIdx.x >> 6;
        int n = threadIdx.x & 63;
        int i = blockIdx.x * 4 + sub;
        if (n < DD) xs[sub][n] = X[i * DD + n];
        __syncthreads();
        float hs = 0.f, hd = b1[n];
        #pragma unroll
        for (int d = 0; d < DD; d++) {
            float xv = xs[sub][d];
            hs = fmaf(xv, W1[d * HH + n], hs);
            hd = fmaf(xv, W1[(DD + d) * HH + n], hd);
        }
        g_hs[i * HH + n] = hs;
        g_hd[i * HH + n] = hd;
    } else {
        // W2 -> mma.m16n8k16 B-frag image, split fp16 hi/lo.
        // n = nt*8 + lane/4, kq = kk*16 + (lane%4)*2
        int t = (blockIdx.x - 256) * 256 + threadIdx.x;   // 1024 entries
        int lane = t & 31;
        int kk = (t >> 5) & 3;
        int nt = t >> 7;
        int n  = nt * 8 + (lane >> 2);
        int kq = kk * 16 + (lane & 3) * 2;
        float w00 = W2[kq * HH + n],       w01 = W2[(kq + 1) * HH + n];
        float w10 = W2[(kq + 8) * HH + n], w11 = W2[(kq + 9) * HH + n];
        float h00 = h_hi(w00), h01 = h_hi(w01), h10 = h_hi(w10), h11 = h_hi(w11);
        uint4 r;
        r.x = pack_h2(h00, h01);
        r.y = pack_h2(h10, h11);
        r.z = pack_h2(w00 - h00, w01 - h01);
        r.w = pack_h2(w10 - h10, w11 - h11);
        g_w2f[t] = r;
    }
}

// ---------------- main pair kernel ----------------
// CTA: 128 threads (4 warps), tile = 8 i x 16 j = 128 pairs.
// Warp w covers i in {by*8 + 2w, +1}; mma M-rows = 16 j values.
__global__ __launch_bounds__(128) void pair_kernel(
    const float* __restrict__ g1, const float* __restrict__ be1,
    const float* __restrict__ b2, const float* __restrict__ g2,
    const float* __restrict__ be2, const float* __restrict__ W3,
    const float* __restrict__ b3, float* __restrict__ out) {
    __shared__ uint4 s_bf[8 * 4 * 32];   // 16 KB B fragments
    __shared__ float s_g1[HH], s_be1[HH], s_b2[HH], s_g2[HH], s_be2[HH], s_w3[HH];
    __shared__ float s_b3;

    int tid = threadIdx.x;
    int w = tid >> 5, lane = tid & 31;
    int qr = lane >> 2, qc = lane & 3;

    #pragma unroll
    for (int idx = tid; idx < 1024; idx += 128) s_bf[idx] = g_w2f[idx];
    if (tid < HH) {
        s_g1[tid]  = g1[tid];
        s_be1[tid] = be1[tid];
        s_b2[tid]  = b2[tid];
        s_g2[tid]  = g2[tid];
        s_be2[tid] = be2[tid];
        s_w3[tid]  = W3[tid];
    }
    if (tid == 0) s_b3 = b3[0];
    __syncthreads();

    int bx = blockIdx.x, by = blockIdx.y;

    #pragma unroll
    for (int mt = 0; mt < 2; mt++) {
        int i  = by * 8 + w * 2 + mt;
        int j1 = bx * 16 + qr;            // mma row r; row r+8 -> j1+8

        const float2* hsp = reinterpret_cast<const float2*>(g_hs + i * HH);
        const float2* hd1 = reinterpret_cast<const float2*>(g_hd + j1 * HH);
        const float2* hd2 = reinterpret_cast<const float2*>(g_hd + (j1 + 8) * HH);

        // ---- x = hs[i] + hd[j] at this lane's 16 fragment columns; LN1 stats ----
        float x1[16], x2[16];
        float s11 = 0.f, s12 = 0.f, s21 = 0.f, s22 = 0.f;
        #pragma unroll
        for (int kk = 0; kk < 4; kk++) {
            #pragma unroll
            for (int h = 0; h < 2; h++) {
                int c2 = (kk * 16 + h * 8 + qc * 2) >> 1;   // float2 index
                float2 a  = hsp[c2];
                float2 d1 = hd1[c2];
                float2 d2 = hd2[c2];
                int o = kk * 4 + h * 2;
                float v1a = a.x + d1.x, v1b = a.y + d1.y;
                float v2a = a.x + d2.x, v2b = a.y + d2.y;
                x1[o] = v1a; x1[o + 1] = v1b;
                x2[o] = v2a; x2[o + 1] = v2b;
                s11 += v1a + v1b; s12 += v1a * v1a + v1b * v1b;
                s21 += v2a + v2b; s22 += v2a * v2a + v2b * v2b;
            }
        }
        s11 = qred(s11); s12 = qred(s12);
        s21 = qred(s21); s22 = qred(s22);
        float mu1 = s11 * (1.f / HH);
        float rs1 = rsqrtf(s12 * (1.f / HH) - mu1 * mu1 + LN_EPS);
        float mu2 = s21 * (1.f / HH);
        float rs2 = rsqrtf(s22 * (1.f / HH) - mu2 * mu2 + LN_EPS);

        // ---- v = relu(LN1(x)) -> fp16 A fragments (hi only; W carries the lo) ----
        uint32_t af[4][4];
        #pragma unroll
        for (int kk = 0; kk < 4; kk++) {
            #pragma unroll
            for (int h = 0; h < 2; h++) {
                int c = kk * 16 + h * 8 + qc * 2;
                int o = kk * 4 + h * 2;
                float2 g1c  = *reinterpret_cast<const float2*>(s_g1 + c);
                float2 be1c = *reinterpret_cast<const float2*>(s_be1 + c);
                float v1a = fmaxf(fmaf((x1[o]     - mu1) * rs1, g1c.x, be1c.x), 0.f);
                float v1b = fmaxf(fmaf((x1[o + 1] - mu1) * rs1, g1c.y, be1c.y), 0.f);
                float v2a = fmaxf(fmaf((x2[o]     - mu2) * rs2, g1c.x, be1c.x), 0.f);
                float v2b = fmaxf(fmaf((x2[o + 1] - mu2) * rs2, g1c.y, be1c.y), 0.f);
                af[kk][h * 2]     = pack_h2(v1a, v1b);   // row r
                af[kk][h * 2 + 1] = pack_h2(v2a, v2b);   // row r+8
            }
        }

        // ---- u = v @ W2 via 2-pass split-fp16 mma (A·Whi + A·Wlo) ----
        float acc[8][4];
        #pragma unroll
        for (int nt = 0; nt < 8; nt++)
            #pragma unroll
            for (int e = 0; e < 4; e++) acc[nt][e] = 0.f;
        #pragma unroll
        for (int nt = 0; nt < 8; nt++) {
            #pragma unroll
            for (int kk = 0; kk < 4; kk++) {
                uint4 B = s_bf[(nt * 4 + kk) * 32 + lane];
                mma_f16(acc[nt], af[kk][0], af[kk][1], af[kk][2], af[kk][3], B.x, B.y); // A * W_hi
                mma_f16(acc[nt], af[kk][0], af[kk][1], af[kk][2], af[kk][3], B.z, B.w); // A * W_lo
            }
        }

        // ---- epilogue: +b2, LN2, relu, dot(W3), sigmoid ----
        float u1[16], u2[16];
        float t11 = 0.f, t12 = 0.f, t21 = 0.f, t22 = 0.f;
        #pragma unroll
        for (int nt = 0; nt < 8; nt++) {
            int c = nt * 8 + qc * 2;
            float2 b2c = *reinterpret_cast<const float2*>(s_b2 + c);
            float va = acc[nt][0] + b2c.x, vb = acc[nt][1] + b2c.y;
            float wa = acc[nt][2] + b2c.x, wb = acc[nt][3] + b2c.y;
            u1[nt * 2] = va; u1[nt * 2 + 1] = vb;
            u2[nt * 2] = wa; u2[nt * 2 + 1] = wb;
            t11 += va + vb; t12 += va * va + vb * vb;
            t21 += wa + wb; t22 += wa * wa + wb * wb;
        }
        t11 = qred(t11); t12 = qred(t12);
        t21 = qred(t21); t22 = qred(t22);
        float m1 = t11 * (1.f / HH);
        float r1 = rsqrtf(t12 * (1.f / HH) - m1 * m1 + LN_EPS);
        float m2 = t21 * (1.f / HH);
        float r2 = rsqrtf(t22 * (1.f / HH) - m2 * m2 + LN_EPS);

        float d1 = 0.f, d2 = 0.f;
        #pragma unroll
        for (int nt = 0; nt < 8; nt++) {
            int c = nt * 8 + qc * 2;
            float2 g2c  = *reinterpret_cast<const float2*>(s_g2 + c);
            float2 be2c = *reinterpret_cast<const float2*>(s_be2 + c);
            float2 w3c  = *reinterpret_cast<const float2*>(s_w3 + c);
            float z;
            z = fmaxf(fmaf((u1[nt * 2]     - m1) * r1, g2c.x, be2c.x), 0.f); d1 = fmaf(z, w3c.x, d1);
            z = fmaxf(fmaf((u1[nt * 2 + 1] - m1) * r1, g2c.y, be2c.y), 0.f); d1 = fmaf(z, w3c.y, d1);
            z = fmaxf(fmaf((u2[nt * 2]     - m2) * r2, g2c.x, be2c.x), 0.f); d2 = fmaf(z, w3c.x, d2);
            z = fmaxf(fmaf((u2[nt * 2 + 1] - m2) * r2, g2c.y, be2c.y), 0.f); d2 = fmaf(z, w3c.y, d2);
        }
        d1 = qred(d1); d2 = qred(d2);
        if (qc == 0) {
            out[i * NN + j1]     = 1.f / (1.f + __expf(-(d1 + s_b3)));
            out[i * NN + j1 + 8] = 1.f / (1.f + __expf(-(d2 + s_b3)));
        }
    }
}

// ---------------- launch ----------------
extern "C" void kernel_launch(void* const* d_in, const int* in_sizes, int n_in,
                              void* d_out, int out_size) {
    const float* X   = (const float*)d_in[0];
    const float* W1  = (const float*)d_in[1];
    const float* b1  = (const float*)d_in[2];
    const float* g1  = (const float*)d_in[3];
    const float* be1 = (const float*)d_in[4];
    const float* W2  = (const float*)d_in[5];
    const float* b2  = (const float*)d_in[6];
    const float* g2  = (const float*)d_in[7];
    const float* be2 = (const float*)d_in[8];
    const float* W3  = (const float*)d_in[9];
    const float* b3  = (const float*)d_in[10];
    float* out = (float*)d_out;

    prep_all<<<260, 256>>>(X, W1, b1, W2);
    dim3 grid(NN / 16, NN / 8);
    pair_kernel<<<grid, 128>>>(g1, be1, b2, g2, be2, W3, b3, out);
}

// round 5
// speedup vs baseline: 5.1368x; 1.4422x over previous
#include <cuda_runtime.h>
#include <cuda_fp16.h>
#include <cstdint>

#define NN 1024
#define DD 32
#define HH 64
#define LN_EPS 1e-5f
#define PADH 68   // smem row stride (floats): bank = (4*qr+2*qc)%32 -> max 2-way

// ---------------- device globals ----------------
__device__ float g_hs[NN * HH];       // X @ W1[:32]
__device__ float g_hd[NN * HH];       // X @ W1[32:] + b1
__device__ uint2 g_w2f[8 * 4 * 32];   // fp16 W2 B-frags: [nt][kk][lane] = {b0,b1}

// ---------------- helpers ----------------
__device__ __forceinline__ uint32_t pack_h2(float a, float b) {
    __half2 t = __floats2half2_rn(a, b);
    return *reinterpret_cast<uint32_t*>(&t);
}
__device__ __forceinline__ void mma_f16(float* c, uint32_t a0, uint32_t a1,
                                        uint32_t a2, uint32_t a3,
                                        uint32_t b0, uint32_t b1) {
    asm volatile(
        "mma.sync.aligned.m16n8k16.row.col.f32.f16.f16.f32 "
        "{%0,%1,%2,%3}, {%4,%5,%6,%7}, {%8,%9}, {%0,%1,%2,%3};"
        : "+f"(c[0]), "+f"(c[1]), "+f"(c[2]), "+f"(c[3])
        : "r"(a0), "r"(a1), "r"(a2), "r"(a3), "r"(b0), "r"(b1));
}
__device__ __forceinline__ float qred(float v) {
    v += __shfl_xor_sync(0xffffffffu, v, 1);
    v += __shfl_xor_sync(0xffffffffu, v, 2);
    return v;
}

// ---------------- merged prep ----------------
__global__ void prep_all(const float* __restrict__ X,
                         const float* __restrict__ W1,
                         const float* __restrict__ b1,
                         const float* __restrict__ W2) {
    if (blockIdx.x < 256) {
        __shared__ float xs[4][DD];
        int sub = threadIdx.x >> 6;
        int n = threadIdx.x & 63;
        int i = blockIdx.x * 4 + sub;
        if (n < DD) xs[sub][n] = X[i * DD + n];
        __syncthreads();
        float hs = 0.f, hd = b1[n];
        #pragma unroll
        for (int d = 0; d < DD; d++) {
            float xv = xs[sub][d];
            hs = fmaf(xv, W1[d * HH + n], hs);
            hd = fmaf(xv, W1[(DD + d) * HH + n], hd);
        }
        g_hs[i * HH + n] = hs;
        g_hd[i * HH + n] = hd;
    } else {
        // W2 -> mma.m16n8k16 B-frag (fp16): n = nt*8+lane/4, kq = kk*16+(lane%4)*2
        int t = (blockIdx.x - 256) * 256 + threadIdx.x;   // 1024 entries
        if (t >= 1024) return;
        int lane = t & 31;
        int kk = (t >> 5) & 3;
        int nt = t >> 7;
        int n  = nt * 8 + (lane >> 2);
        int kq = kk * 16 + (lane & 3) * 2;
        uint2 r;
        r.x = pack_h2(W2[kq * HH + n],       W2[(kq + 1) * HH + n]);
        r.y = pack_h2(W2[(kq + 8) * HH + n], W2[(kq + 9) * HH + n]);
        g_w2f[t] = r;
    }
}

// ---------------- main pair kernel ----------------
// CTA: 128 threads (4 warps), tile = 8 i x 16 j. Warp w: i = by*8 + 2w + mt.
__global__ __launch_bounds__(128) void pair_kernel(
    const float* __restrict__ g1, const float* __restrict__ be1,
    const float* __restrict__ b2, const float* __restrict__ g2,
    const float* __restrict__ be2, const float* __restrict__ W3,
    const float* __restrict__ b3, float* __restrict__ out) {
    __shared__ uint2 s_bf[8 * 4 * 32];   // 8 KB fp16 B fragments
    __shared__ float s_hd[16 * PADH];    // CTA's 16 hd rows, padded
    __shared__ float s_hs[8 * PADH];     // CTA's 8 hs rows, padded
    __shared__ float s_g1[HH], s_be1[HH], s_b2[HH], s_g2[HH], s_be2[HH], s_w3[HH];
    __shared__ float s_b3;

    int tid = threadIdx.x;
    int w = tid >> 5, lane = tid & 31;
    int qr = lane >> 2, qc = lane & 3;
    int bx = blockIdx.x, by = blockIdx.y;

    #pragma unroll
    for (int idx = tid; idx < 1024; idx += 128) s_bf[idx] = g_w2f[idx];
    #pragma unroll
    for (int idx = tid; idx < 16 * 64; idx += 128) {
        int r = idx >> 6, c = idx & 63;
        s_hd[r * PADH + c] = g_hd[(bx * 16 + r) * HH + c];
    }
    #pragma unroll
    for (int idx = tid; idx < 8 * 64; idx += 128) {
        int r = idx >> 6, c = idx & 63;
        s_hs[r * PADH + c] = g_hs[(by * 8 + r) * HH + c];
    }
    if (tid < HH) {
        s_g1[tid]  = g1[tid];
        s_be1[tid] = be1[tid];
        s_b2[tid]  = b2[tid];
        s_g2[tid]  = g2[tid];
        s_be2[tid] = be2[tid];
        s_w3[tid]  = W3[tid];
    }
    if (tid == 0) s_b3 = b3[0];
    __syncthreads();

    // ---- prologue: A fragments for both mtiles ----
    uint32_t af[2][4][4];
    #pragma unroll
    for (int mt = 0; mt < 2; mt++) {
        const float* hsr  = s_hs + (w * 2 + mt) * PADH;
        const float* hdr1 = s_hd + qr * PADH;
        const float* hdr2 = s_hd + (qr + 8) * PADH;

        float x1[16], x2[16];
        float s11 = 0.f, s12 = 0.f, s21 = 0.f, s22 = 0.f;
        #pragma unroll
        for (int kk = 0; kk < 4; kk++) {
            #pragma unroll
            for (int h = 0; h < 2; h++) {
                int c = kk * 16 + h * 8 + qc * 2;
                float2 a  = *reinterpret_cast<const float2*>(hsr + c);
                float2 d1 = *reinterpret_cast<const float2*>(hdr1 + c);
                float2 d2 = *reinterpret_cast<const float2*>(hdr2 + c);
                int o = kk * 4 + h * 2;
                float v1a = a.x + d1.x, v1b = a.y + d1.y;
                float v2a = a.x + d2.x, v2b = a.y + d2.y;
                x1[o] = v1a; x1[o + 1] = v1b;
                x2[o] = v2a; x2[o + 1] = v2b;
                s11 += v1a + v1b; s12 += v1a * v1a + v1b * v1b;
                s21 += v2a + v2b; s22 += v2a * v2a + v2b * v2b;
            }
        }
        s11 = qred(s11); s12 = qred(s12);
        s21 = qred(s21); s22 = qred(s22);
        float mu1 = s11 * (1.f / HH);
        float rs1 = rsqrtf(s12 * (1.f / HH) - mu1 * mu1 + LN_EPS);
        float mu2 = s21 * (1.f / HH);
        float rs2 = rsqrtf(s22 * (1.f / HH) - mu2 * mu2 + LN_EPS);

        #pragma unroll
        for (int kk = 0; kk < 4; kk++) {
            #pragma unroll
            for (int h = 0; h < 2; h++) {
                int c = kk * 16 + h * 8 + qc * 2;
                int o = kk * 4 + h * 2;
                float2 g1c  = *reinterpret_cast<const float2*>(s_g1 + c);
                float2 be1c = *reinterpret_cast<const float2*>(s_be1 + c);
                float v1a = fmaxf(fmaf((x1[o]     - mu1) * rs1, g1c.x, be1c.x), 0.f);
                float v1b = fmaxf(fmaf((x1[o + 1] - mu1) * rs1, g1c.y, be1c.y), 0.f);
                float v2a = fmaxf(fmaf((x2[o]     - mu2) * rs2, g1c.x, be1c.x), 0.f);
                float v2b = fmaxf(fmaf((x2[o + 1] - mu2) * rs2, g1c.y, be1c.y), 0.f);
                af[mt][kk][h * 2]     = pack_h2(v1a, v1b);   // row r
                af[mt][kk][h * 2 + 1] = pack_h2(v2a, v2b);   // row r+8
            }
        }
    }

    // ---- fused MMA: each B fragment loaded once, used by both mtiles ----
    float acc[2][8][4];
    #pragma unroll
    for (int mt = 0; mt < 2; mt++)
        #pragma unroll
        for (int nt = 0; nt < 8; nt++)
            #pragma unroll
            for (int e = 0; e < 4; e++) acc[mt][nt][e] = 0.f;
    #pragma unroll
    for (int nt = 0; nt < 8; nt++) {
        #pragma unroll
        for (int kk = 0; kk < 4; kk++) {
            uint2 B = s_bf[(nt * 4 + kk) * 32 + lane];
            mma_f16(acc[0][nt], af[0][kk][0], af[0][kk][1], af[0][kk][2], af[0][kk][3], B.x, B.y);
            mma_f16(acc[1][nt], af[1][kk][0], af[1][kk][1], af[1][kk][2], af[1][kk][3], B.x, B.y);
        }
    }

    // ---- epilogue per mtile ----
    #pragma unroll
    for (int mt = 0; mt < 2; mt++) {
        int i  = by * 8 + w * 2 + mt;
        int j1 = bx * 16 + qr;

        float u1[16], u2[16];
        float t11 = 0.f, t12 = 0.f, t21 = 0.f, t22 = 0.f;
        #pragma unroll
        for (int nt = 0; nt < 8; nt++) {
            int c = nt * 8 + qc * 2;
            float2 b2c = *reinterpret_cast<const float2*>(s_b2 + c);
            float va = acc[mt][nt][0] + b2c.x, vb = acc[mt][nt][1] + b2c.y;
            float wa = acc[mt][nt][2] + b2c.x, wb = acc[mt][nt][3] + b2c.y;
            u1[nt * 2] = va; u1[nt * 2 + 1] = vb;
            u2[nt * 2] = wa; u2[nt * 2 + 1] = wb;
            t11 += va + vb; t12 += va * va + vb * vb;
            t21 += wa + wb; t22 += wa * wa + wb * wb;
        }
        t11 = qred(t11); t12 = qred(t12);
        t21 = qred(t21); t22 = qred(t22);
        float m1 = t11 * (1.f / HH);
        float r1 = rsqrtf(t12 * (1.f / HH) - m1 * m1 + LN_EPS);
        float m2 = t21 * (1.f / HH);
        float r2 = rsqrtf(t22 * (1.f / HH) - m2 * m2 + LN_EPS);

        float d1 = 0.f, d2 = 0.f;
        #pragma unroll
        for (int nt = 0; nt < 8; nt++) {
            int c = nt * 8 + qc * 2;
            float2 g2c  = *reinterpret_cast<const float2*>(s_g2 + c);
            float2 be2c = *reinterpret_cast<const float2*>(s_be2 + c);
            float2 w3c  = *reinterpret_cast<const float2*>(s_w3 + c);
            float z;
            z = fmaxf(fmaf((u1[nt * 2]     - m1) * r1, g2c.x, be2c.x), 0.f); d1 = fmaf(z, w3c.x, d1);
            z = fmaxf(fmaf((u1[nt * 2 + 1] - m1) * r1, g2c.y, be2c.y), 0.f); d1 = fmaf(z, w3c.y, d1);
            z = fmaxf(fmaf((u2[nt * 2]     - m2) * r2, g2c.x, be2c.x), 0.f); d2 = fmaf(z, w3c.x, d2);
            z = fmaxf(fmaf((u2[nt * 2 + 1] - m2) * r2, g2c.y, be2c.y), 0.f); d2 = fmaf(z, w3c.y, d2);
        }
        d1 = qred(d1); d2 = qred(d2);
        if (qc == 0) {
            out[i * NN + j1]     = 1.f / (1.f + __expf(-(d1 + s_b3)));
            out[i * NN + j1 + 8] = 1.f / (1.f + __expf(-(d2 + s_b3)));
        }
    }
}

// ---------------- launch ----------------
extern "C" void kernel_launch(void* const* d_in, const int* in_sizes, int n_in,
                              void* d_out, int out_size) {
    const float* X   = (const float*)d_in[0];
    const float* W1  = (const float*)d_in[1];
    const float* b1  = (const float*)d_in[2];
    const float* g1  = (const float*)d_in[3];
    const float* be1 = (const float*)d_in[4];
    const float* W2  = (const float*)d_in[5];
    const float* b2  = (const float*)d_in[6];
    const float* g2  = (const float*)d_in[7];
    const float* be2 = (const float*)d_in[8];
    const float* W3  = (const float*)d_in[9];
    const float* b3  = (const float*)d_in[10];
    float* out = (float*)d_out;

    prep_all<<<260, 256>>>(X, W1, b1, W2);
    dim3 grid(NN / 16, NN / 8);
    pair_kernel<<<grid, 128>>>(g1, be1, b2, g2, be2, W3, b3, out);
}

// round 6
// speedup vs baseline: 5.4345x; 1.0580x over previous
#include <cuda_runtime.h>
#include <cuda_fp16.h>
#include <cstdint>

#define NN 1024
#define DD 32
#define HH 64
#define LN_EPS 1e-5f
#define PADH 68   // smem row stride (floats): bank = (4*qr+2*qc)%32 -> max 2-way

typedef unsigned long long ull;

// ---------------- device globals ----------------
__device__ float g_hs[NN * HH];       // X @ W1[:32]
__device__ float g_hd[NN * HH];       // X @ W1[32:] + b1
__device__ uint2 g_w2f[8 * 4 * 32];   // fp16 W2 B-frags: [nt][kk][lane] = {b0,b1}

// ---------------- packed f32x2 helpers (Blackwell FFMA2 path) ----------------
__device__ __forceinline__ ull p2_add(ull a, ull b) {
    ull r; asm("add.rn.f32x2 %0, %1, %2;" : "=l"(r) : "l"(a), "l"(b)); return r;
}
__device__ __forceinline__ ull p2_fma(ull a, ull b, ull c) {
    ull r; asm("fma.rn.f32x2 %0, %1, %2, %3;" : "=l"(r) : "l"(a), "l"(b), "l"(c)); return r;
}
__device__ __forceinline__ ull p2_pack(float lo, float hi) {
    ull r; asm("mov.b64 %0, {%1, %2};" : "=l"(r) : "f"(lo), "f"(hi)); return r;
}
__device__ __forceinline__ void p2_unpack(ull v, float& lo, float& hi) {
    asm("mov.b64 {%0, %1}, %2;" : "=f"(lo), "=f"(hi) : "l"(v));
}
__device__ __forceinline__ uint32_t pack_h2(float a, float b) {
    __half2 t = __floats2half2_rn(a, b);
    return *reinterpret_cast<uint32_t*>(&t);
}
__device__ __forceinline__ void mma_f16(float* c, uint32_t a0, uint32_t a1,
                                        uint32_t a2, uint32_t a3,
                                        uint32_t b0, uint32_t b1) {
    asm volatile(
        "mma.sync.aligned.m16n8k16.row.col.f32.f16.f16.f32 "
        "{%0,%1,%2,%3}, {%4,%5,%6,%7}, {%8,%9}, {%0,%1,%2,%3};"
        : "+f"(c[0]), "+f"(c[1]), "+f"(c[2]), "+f"(c[3])
        : "r"(a0), "r"(a1), "r"(a2), "r"(a3), "r"(b0), "r"(b1));
}
__device__ __forceinline__ float qred(float v) {
    v += __shfl_xor_sync(0xffffffffu, v, 1);
    v += __shfl_xor_sync(0xffffffffu, v, 2);
    return v;
}

// ---------------- merged prep ----------------
__global__ void prep_all(const float* __restrict__ X,
                         const float* __restrict__ W1,
                         const float* __restrict__ b1,
                         const float* __restrict__ W2) {
    if (blockIdx.x < 256) {
        __shared__ float xs[4][DD];
        int sub = threadIdx.x >> 6;
        int n = threadIdx.x & 63;
        int i = blockIdx.x * 4 + sub;
        if (n < DD) xs[sub][n] = X[i * DD + n];
        __syncthreads();
        float hs = 0.f, hd = b1[n];
        #pragma unroll
        for (int d = 0; d < DD; d++) {
            float xv = xs[sub][d];
            hs = fmaf(xv, W1[d * HH + n], hs);
            hd = fmaf(xv, W1[(DD + d) * HH + n], hd);
        }
        g_hs[i * HH + n] = hs;
        g_hd[i * HH + n] = hd;
    } else {
        int t = (blockIdx.x - 256) * 256 + threadIdx.x;
        if (t >= 1024) return;
        int lane = t & 31;
        int kk = (t >> 5) & 3;
        int nt = t >> 7;
        int n  = nt * 8 + (lane >> 2);
        int kq = kk * 16 + (lane & 3) * 2;
        uint2 r;
        r.x = pack_h2(W2[kq * HH + n],       W2[(kq + 1) * HH + n]);
        r.y = pack_h2(W2[(kq + 8) * HH + n], W2[(kq + 9) * HH + n]);
        g_w2f[t] = r;
    }
}

// ---------------- main pair kernel ----------------
__global__ __launch_bounds__(128) void pair_kernel(
    const float* __restrict__ g1, const float* __restrict__ be1,
    const float* __restrict__ b2, const float* __restrict__ g2,
    const float* __restrict__ be2, const float* __restrict__ W3,
    const float* __restrict__ b3, float* __restrict__ out) {
    __shared__ uint2 s_bf[8 * 4 * 32];
    __shared__ __align__(16) float s_hd[16 * PADH];
    __shared__ __align__(16) float s_hs[8 * PADH];
    __shared__ __align__(8) float s_g1[HH];
    __shared__ __align__(8) float s_be1[HH];
    __shared__ __align__(8) float s_b2[HH];
    __shared__ __align__(8) float s_g2[HH];
    __shared__ __align__(8) float s_be2[HH];
    __shared__ __align__(8) float s_w3[HH];
    __shared__ float s_b3;

    int tid = threadIdx.x;
    int w = tid >> 5, lane = tid & 31;
    int qr = lane >> 2, qc = lane & 3;
    int bx = blockIdx.x, by = blockIdx.y;

    #pragma unroll
    for (int idx = tid; idx < 1024; idx += 128) s_bf[idx] = g_w2f[idx];
    #pragma unroll
    for (int idx = tid; idx < 16 * 64; idx += 128) {
        int r = idx >> 6, c = idx & 63;
        s_hd[r * PADH + c] = g_hd[(bx * 16 + r) * HH + c];
    }
    #pragma unroll
    for (int idx = tid; idx < 8 * 64; idx += 128) {
        int r = idx >> 6, c = idx & 63;
        s_hs[r * PADH + c] = g_hs[(by * 8 + r) * HH + c];
    }
    if (tid < HH) {
        s_g1[tid]  = g1[tid];
        s_be1[tid] = be1[tid];
        s_b2[tid]  = b2[tid];
        s_g2[tid]  = g2[tid];
        s_be2[tid] = be2[tid];
        s_w3[tid]  = W3[tid];
    }
    if (tid == 0) s_b3 = b3[0];
    __syncthreads();

    // ---- load the 4 input rows once (packed float2 per lane column) ----
    const float* hsr0 = s_hs + (w * 2) * PADH;
    const float* hsr1 = s_hs + (w * 2 + 1) * PADH;
    const float* hdr1 = s_hd + qr * PADH;
    const float* hdr2 = s_hd + (qr + 8) * PADH;
    ull a0[8], a1[8], dA[8], dB[8];
    #pragma unroll
    for (int ci = 0; ci < 8; ci++) {
        int c = (ci >> 1) * 16 + (ci & 1) * 8 + qc * 2;
        a0[ci] = *reinterpret_cast<const ull*>(hsr0 + c);
        a1[ci] = *reinterpret_cast<const ull*>(hsr1 + c);
        dA[ci] = *reinterpret_cast<const ull*>(hdr1 + c);
        dB[ci] = *reinterpret_cast<const ull*>(hdr2 + c);
    }

    // ---- prologue: 4 (mt,row) combos, packed LN1 -> fp16 A frags ----
    uint32_t af[2][4][4];
    #pragma unroll
    for (int combo = 0; combo < 4; combo++) {
        int mt = combo >> 1, rr = combo & 1;
        const ull* A = mt ? a1 : a0;
        const ull* D = rr ? dB : dA;
        ull x[8];
        ull s1p = 0ull, s2p = 0ull;
        #pragma unroll
        for (int ci = 0; ci < 8; ci++) {
            x[ci] = p2_add(A[ci], D[ci]);
            s1p = p2_add(s1p, x[ci]);
            s2p = p2_fma(x[ci], x[ci], s2p);
        }
        float lo, hi;
        p2_unpack(s1p, lo, hi); float s1 = qred(lo + hi);
        p2_unpack(s2p, lo, hi); float s2 = qred(lo + hi);
        float mu = s1 * (1.f / HH);
        float rs = rsqrtf(s2 * (1.f / HH) - mu * mu + LN_EPS);
        ull rsp = p2_pack(rs, rs);
        ull nmp = p2_pack(-mu * rs, -mu * rs);
        #pragma unroll
        for (int ci = 0; ci < 8; ci++) {
            int kk = ci >> 1, h = ci & 1;
            int c = kk * 16 + h * 8 + qc * 2;
            ull gp = *reinterpret_cast<const ull*>(s_g1 + c);
            ull bp = *reinterpret_cast<const ull*>(s_be1 + c);
            ull t = p2_fma(x[ci], rsp, nmp);
            ull v = p2_fma(t, gp, bp);
            float va, vb;
            p2_unpack(v, va, vb);
            af[mt][kk][h * 2 + rr] = pack_h2(fmaxf(va, 0.f), fmaxf(vb, 0.f));
        }
    }

    // ---- fused MMA: each B fragment loaded once, used by both mtiles ----
    float acc[2][8][4];
    #pragma unroll
    for (int mt = 0; mt < 2; mt++)
        #pragma unroll
        for (int nt = 0; nt < 8; nt++)
            #pragma unroll
            for (int e = 0; e < 4; e++) acc[mt][nt][e] = 0.f;
    #pragma unroll
    for (int nt = 0; nt < 8; nt++) {
        #pragma unroll
        for (int kk = 0; kk < 4; kk++) {
            uint2 B = s_bf[(nt * 4 + kk) * 32 + lane];
            mma_f16(acc[0][nt], af[0][kk][0], af[0][kk][1], af[0][kk][2], af[0][kk][3], B.x, B.y);
            mma_f16(acc[1][nt], af[1][kk][0], af[1][kk][1], af[1][kk][2], af[1][kk][3], B.x, B.y);
        }
    }

    // ---- epilogue per mtile (packed) ----
    #pragma unroll
    for (int mt = 0; mt < 2; mt++) {
        int i  = by * 8 + w * 2 + mt;
        int j1 = bx * 16 + qr;

        ull u1p[8], u2p[8];
        ull t11p = 0ull, t12p = 0ull, t21p = 0ull, t22p = 0ull;
        #pragma unroll
        for (int nt = 0; nt < 8; nt++) {
            int c = nt * 8 + qc * 2;
            ull b2p = *reinterpret_cast<const ull*>(s_b2 + c);
            ull ua = p2_add(p2_pack(acc[mt][nt][0], acc[mt][nt][1]), b2p);
            ull ub = p2_add(p2_pack(acc[mt][nt][2], acc[mt][nt][3]), b2p);
            u1p[nt] = ua; u2p[nt] = ub;
            t11p = p2_add(t11p, ua); t12p = p2_fma(ua, ua, t12p);
            t21p = p2_add(t21p, ub); t22p = p2_fma(ub, ub, t22p);
        }
        float lo, hi;
        p2_unpack(t11p, lo, hi); float t11 = qred(lo + hi);
        p2_unpack(t12p, lo, hi); float t12 = qred(lo + hi);
        p2_unpack(t21p, lo, hi); float t21 = qred(lo + hi);
        p2_unpack(t22p, lo, hi); float t22 = qred(lo + hi);
        float m1 = t11 * (1.f / HH);
        float r1 = rsqrtf(t12 * (1.f / HH) - m1 * m1 + LN_EPS);
        float m2 = t21 * (1.f / HH);
        float r2 = rsqrtf(t22 * (1.f / HH) - m2 * m2 + LN_EPS);
        ull r1p = p2_pack(r1, r1), nm1p = p2_pack(-m1 * r1, -m1 * r1);
        ull r2p = p2_pack(r2, r2), nm2p = p2_pack(-m2 * r2, -m2 * r2);

        ull d1p = 0ull, d2p = 0ull;
        #pragma unroll
        for (int nt = 0; nt < 8; nt++) {
            int c = nt * 8 + qc * 2;
            ull g2p  = *reinterpret_cast<const ull*>(s_g2 + c);
            ull be2p = *reinterpret_cast<const ull*>(s_be2 + c);
            ull w3p  = *reinterpret_cast<const ull*>(s_w3 + c);
            float za, zb;
            ull z1 = p2_fma(p2_fma(u1p[nt], r1p, nm1p), g2p, be2p);
            p2_unpack(z1, za, zb);
            d1p = p2_fma(p2_pack(fmaxf(za, 0.f), fmaxf(zb, 0.f)), w3p, d1p);
            ull z2 = p2_fma(p2_fma(u2p[nt], r2p, nm2p), g2p, be2p);
            p2_unpack(z2, za, zb);
            d2p = p2_fma(p2_pack(fmaxf(za, 0.f), fmaxf(zb, 0.f)), w3p, d2p);
        }
        p2_unpack(d1p, lo, hi); float d1 = qred(lo + hi);
        p2_unpack(d2p, lo, hi); float d2 = qred(lo + hi);
        if (qc == 0) {
            out[i * NN + j1]     = 1.f / (1.f + __expf(-(d1 + s_b3)));
            out[i * NN + j1 + 8] = 1.f / (1.f + __expf(-(d2 + s_b3)));
        }
    }
}

// ---------------- launch ----------------
extern "C" void kernel_launch(void* const* d_in, const int* in_sizes, int n_in,
                              void* d_out, int out_size) {
    const float* X   = (const float*)d_in[0];
    const float* W1  = (const float*)d_in[1];
    const float* b1  = (const float*)d_in[2];
    const float* g1  = (const float*)d_in[3];
    const float* be1 = (const float*)d_in[4];
    const float* W2  = (const float*)d_in[5];
    const float* b2  = (const float*)d_in[6];
    const float* g2  = (const float*)d_in[7];
    const float* be2 = (const float*)d_in[8];
    const float* W3  = (const float*)d_in[9];
    const float* b3  = (const float*)d_in[10];
    float* out = (float*)d_out;

    prep_all<<<260, 256>>>(X, W1, b1, W2);
    dim3 grid(NN / 16, NN / 8);
    pair_kernel<<<grid, 128>>>(g1, be1, b2, g2, be2, W3, b3, out);
}

// round 7
// speedup vs baseline: 5.7717x; 1.0620x over previous
#include <cuda_runtime.h>
#include <cuda_fp16.h>
#include <cstdint>

#define NN 1024
#define DD 32
#define HH 64
#define LN_EPS 1e-5f
#define PADH 68   // smem row stride (floats): max 2-way conflicts

typedef unsigned long long ull;

// ---------------- device globals ----------------
__device__ float g_hs[NN * HH];       // X @ W1[:32]
__device__ float g_hd[NN * HH];       // X @ W1[32:] + b1
__device__ float g_hsum[NN];          // row sums of g_hs
__device__ float g_dsum[NN];          // row sums of g_hd
__device__ uint2 g_w2f[8 * 4 * 32];   // fp16 W2 B-frags: [nt][kk][lane] = {b0,b1}

// ---------------- packed f32x2 helpers ----------------
__device__ __forceinline__ ull p2_add(ull a, ull b) {
    ull r; asm("add.rn.f32x2 %0, %1, %2;" : "=l"(r) : "l"(a), "l"(b)); return r;
}
__device__ __forceinline__ ull p2_fma(ull a, ull b, ull c) {
    ull r; asm("fma.rn.f32x2 %0, %1, %2, %3;" : "=l"(r) : "l"(a), "l"(b), "l"(c)); return r;
}
__device__ __forceinline__ ull p2_pack(float lo, float hi) {
    ull r; asm("mov.b64 %0, {%1, %2};" : "=l"(r) : "f"(lo), "f"(hi)); return r;
}
__device__ __forceinline__ void p2_unpack(ull v, float& lo, float& hi) {
    asm("mov.b64 {%0, %1}, %2;" : "=f"(lo), "=f"(hi) : "l"(v));
}
__device__ __forceinline__ uint32_t pack_h2(float a, float b) {
    __half2 t = __floats2half2_rn(a, b);
    return *reinterpret_cast<uint32_t*>(&t);
}
__device__ __forceinline__ void mma_f16(float* c, uint32_t a0, uint32_t a1,
                                        uint32_t a2, uint32_t a3,
                                        uint32_t b0, uint32_t b1) {
    asm volatile(
        "mma.sync.aligned.m16n8k16.row.col.f32.f16.f16.f32 "
        "{%0,%1,%2,%3}, {%4,%5,%6,%7}, {%8,%9}, {%0,%1,%2,%3};"
        : "+f"(c[0]), "+f"(c[1]), "+f"(c[2]), "+f"(c[3])
        : "r"(a0), "r"(a1), "r"(a2), "r"(a3), "r"(b0), "r"(b1));
}
__device__ __forceinline__ float qred(float v) {
    v += __shfl_xor_sync(0xffffffffu, v, 1);
    v += __shfl_xor_sync(0xffffffffu, v, 2);
    return v;
}
__device__ __forceinline__ float wred32(float v) {
    #pragma unroll
    for (int s = 16; s > 0; s >>= 1) v += __shfl_xor_sync(0xffffffffu, v, s);
    return v;
}

// ---------------- merged prep ----------------
__global__ void prep_all(const float* __restrict__ X,
                         const float* __restrict__ W1,
                         const float* __restrict__ b1,
                         const float* __restrict__ W2) {
    if (blockIdx.x < 256) {
        __shared__ float xs[4][DD];
        __shared__ float red[4][HH];
        int sub = threadIdx.x >> 6;
        int n = threadIdx.x & 63;
        int i = blockIdx.x * 4 + sub;
        if (n < DD) xs[sub][n] = X[i * DD + n];
        __syncthreads();
        float hs = 0.f, hd = b1[n];
        #pragma unroll
        for (int d = 0; d < DD; d++) {
            float xv = xs[sub][d];
            hs = fmaf(xv, W1[d * HH + n], hs);
            hd = fmaf(xv, W1[(DD + d) * HH + n], hd);
        }
        g_hs[i * HH + n] = hs;
        g_hd[i * HH + n] = hd;
        // row sums
        red[sub][n] = hs;
        __syncthreads();
        if (n < 32) {
            float v = red[sub][n] + red[sub][n + 32];
            v = wred32(v);
            if (n == 0) g_hsum[i] = v;
        }
        __syncthreads();
        red[sub][n] = hd;
        __syncthreads();
        if (n < 32) {
            float v = red[sub][n] + red[sub][n + 32];
            v = wred32(v);
            if (n == 0) g_dsum[i] = v;
        }
    } else {
        int t = (blockIdx.x - 256) * 256 + threadIdx.x;
        if (t >= 1024) return;
        int lane = t & 31;
        int kk = (t >> 5) & 3;
        int nt = t >> 7;
        int n  = nt * 8 + (lane >> 2);
        int kq = kk * 16 + (lane & 3) * 2;
        uint2 r;
        r.x = pack_h2(W2[kq * HH + n],       W2[(kq + 1) * HH + n]);
        r.y = pack_h2(W2[(kq + 8) * HH + n], W2[(kq + 9) * HH + n]);
        g_w2f[t] = r;
    }
}

// ---------------- main pair kernel ----------------
__global__ __launch_bounds__(128, 4) void pair_kernel(
    const float* __restrict__ g1, const float* __restrict__ be1,
    const float* __restrict__ b2, const float* __restrict__ g2,
    const float* __restrict__ be2, const float* __restrict__ W3,
    const float* __restrict__ b3, float* __restrict__ out) {
    __shared__ uint2 s_bf[8 * 4 * 32];
    __shared__ __align__(16) float s_hd[16 * PADH];
    __shared__ __align__(16) float s_hs[8 * PADH];
    __shared__ __align__(8) float s_g1[HH];
    __shared__ __align__(8) float s_be1[HH];
    __shared__ __align__(8) float s_b2[HH];
    __shared__ __align__(8) float s_g2[HH];
    __shared__ __align__(8) float s_be2[HH];
    __shared__ __align__(8) float s_w3[HH];
    __shared__ float s_S[8], s_T[16], s_b3;

    int tid = threadIdx.x;
    int w = tid >> 5, lane = tid & 31;
    int qr = lane >> 2, qc = lane & 3;
    int bx = blockIdx.x, by = blockIdx.y;

    #pragma unroll
    for (int idx = tid; idx < 1024; idx += 128) s_bf[idx] = g_w2f[idx];
    #pragma unroll
    for (int idx = tid; idx < 16 * 64; idx += 128) {
        int r = idx >> 6, c = idx & 63;
        s_hd[r * PADH + c] = g_hd[(bx * 16 + r) * HH + c];
    }
    #pragma unroll
    for (int idx = tid; idx < 8 * 64; idx += 128) {
        int r = idx >> 6, c = idx & 63;
        s_hs[r * PADH + c] = g_hs[(by * 8 + r) * HH + c];
    }
    if (tid < HH) {
        s_g1[tid]  = g1[tid];
        s_be1[tid] = be1[tid];
        s_b2[tid]  = b2[tid];
        s_g2[tid]  = g2[tid];
        s_be2[tid] = be2[tid];
        s_w3[tid]  = W3[tid];
    }
    if (tid < 8)  s_S[tid] = g_hsum[by * 8 + tid];
    if (tid < 16) s_T[tid] = g_dsum[bx * 16 + tid];
    if (tid == 0) s_b3 = b3[0];
    __syncthreads();

    // ---- keep only the expensive hd rows in registers ----
    const float* hdr1 = s_hd + qr * PADH;
    const float* hdr2 = s_hd + (qr + 8) * PADH;
    ull dA[8], dB[8];
    #pragma unroll
    for (int ci = 0; ci < 8; ci++) {
        int c = (ci >> 1) * 16 + (ci & 1) * 8 + qc * 2;
        dA[ci] = *reinterpret_cast<const ull*>(hdr1 + c);
        dB[ci] = *reinterpret_cast<const ull*>(hdr2 + c);
    }
    float Tv1 = s_T[qr], Tv2 = s_T[qr + 8];

    // ---- prologue: packed LN1 -> fp16 A frags (s1 from precomputed sums) ----
    uint32_t af[2][4][4];
    #pragma unroll
    for (int mt = 0; mt < 2; mt++) {
        const float* hsr = s_hs + (w * 2 + mt) * PADH;
        ull a[8];
        #pragma unroll
        for (int ci = 0; ci < 8; ci++) {
            int c = (ci >> 1) * 16 + (ci & 1) * 8 + qc * 2;
            a[ci] = *reinterpret_cast<const ull*>(hsr + c);   // broadcast-cheap
        }
        float Sv = s_S[w * 2 + mt];
        #pragma unroll
        for (int rr = 0; rr < 2; rr++) {
            const ull* D = rr ? dB : dA;
            float Tv = rr ? Tv2 : Tv1;
            ull x[8];
            ull s2p = 0ull;
            #pragma unroll
            for (int ci = 0; ci < 8; ci++) {
                x[ci] = p2_add(a[ci], D[ci]);
                s2p = p2_fma(x[ci], x[ci], s2p);
            }
            float lo, hi;
            p2_unpack(s2p, lo, hi);
            float s2 = qred(lo + hi);
            float mu = (Sv + Tv) * (1.f / HH);
            float rs = rsqrtf(s2 * (1.f / HH) - mu * mu + LN_EPS);
            ull rsp = p2_pack(rs, rs);
            ull nmp = p2_pack(-mu * rs, -mu * rs);
            #pragma unroll
            for (int ci = 0; ci < 8; ci++) {
                int kk = ci >> 1, h = ci & 1;
                int c = kk * 16 + h * 8 + qc * 2;
                ull gp = *reinterpret_cast<const ull*>(s_g1 + c);
                ull bp = *reinterpret_cast<const ull*>(s_be1 + c);
                ull v = p2_fma(p2_fma(x[ci], rsp, nmp), gp, bp);
                float va, vb;
                p2_unpack(v, va, vb);
                af[mt][kk][h * 2 + rr] = pack_h2(fmaxf(va, 0.f), fmaxf(vb, 0.f));
            }
        }
    }

    // ---- fused MMA, accumulators initialized with b2 (folds the +b2 add) ----
    float acc[2][8][4];
    #pragma unroll
    for (int nt = 0; nt < 8; nt++) {
        int c = nt * 8 + qc * 2;
        ull b2p = *reinterpret_cast<const ull*>(s_b2 + c);
        float bxv, byv;
        p2_unpack(b2p, bxv, byv);
        #pragma unroll
        for (int mt = 0; mt < 2; mt++) {
            acc[mt][nt][0] = bxv; acc[mt][nt][1] = byv;
            acc[mt][nt][2] = bxv; acc[mt][nt][3] = byv;
        }
    }
    #pragma unroll
    for (int nt = 0; nt < 8; nt++) {
        #pragma unroll
        for (int kk = 0; kk < 4; kk++) {
            uint2 B = s_bf[(nt * 4 + kk) * 32 + lane];
            mma_f16(acc[0][nt], af[0][kk][0], af[0][kk][1], af[0][kk][2], af[0][kk][3], B.x, B.y);
            mma_f16(acc[1][nt], af[1][kk][0], af[1][kk][1], af[1][kk][2], af[1][kk][3], B.x, B.y);
        }
    }

    // ---- epilogue per mtile (packed; u == acc already includes b2) ----
    #pragma unroll
    for (int mt = 0; mt < 2; mt++) {
        int i  = by * 8 + w * 2 + mt;
        int j1 = bx * 16 + qr;

        ull u1p[8], u2p[8];
        ull t11p = 0ull, t12p = 0ull, t21p = 0ull, t22p = 0ull;
        #pragma unroll
        for (int nt = 0; nt < 8; nt++) {
            ull ua = p2_pack(acc[mt][nt][0], acc[mt][nt][1]);
            ull ub = p2_pack(acc[mt][nt][2], acc[mt][nt][3]);
            u1p[nt] = ua; u2p[nt] = ub;
            t11p = p2_add(t11p, ua); t12p = p2_fma(ua, ua, t12p);
            t21p = p2_add(t21p, ub); t22p = p2_fma(ub, ub, t22p);
        }
        float lo, hi;
        p2_unpack(t11p, lo, hi); float t11 = qred(lo + hi);
        p2_unpack(t12p, lo, hi); float t12 = qred(lo + hi);
        p2_unpack(t21p, lo, hi); float t21 = qred(lo + hi);
        p2_unpack(t22p, lo, hi); float t22 = qred(lo + hi);
        float m1 = t11 * (1.f / HH);
        float r1 = rsqrtf(t12 * (1.f / HH) - m1 * m1 + LN_EPS);
        float m2 = t21 * (1.f / HH);
        float r2 = rsqrtf(t22 * (1.f / HH) - m2 * m2 + LN_EPS);
        ull r1p = p2_pack(r1, r1), nm1p = p2_pack(-m1 * r1, -m1 * r1);
        ull r2p = p2_pack(r2, r2), nm2p = p2_pack(-m2 * r2, -m2 * r2);

        ull d1p = 0ull, d2p = 0ull;
        #pragma unroll
        for (int nt = 0; nt < 8; nt++) {
            int c = nt * 8 + qc * 2;
            ull g2p  = *reinterpret_cast<const ull*>(s_g2 + c);
            ull be2p = *reinterpret_cast<const ull*>(s_be2 + c);
            ull w3p  = *reinterpret_cast<const ull*>(s_w3 + c);
            float za, zb;
            ull z1 = p2_fma(p2_fma(u1p[nt], r1p, nm1p), g2p, be2p);
            p2_unpack(z1, za, zb);
            d1p = p2_fma(p2_pack(fmaxf(za, 0.f), fmaxf(zb, 0.f)), w3p, d1p);
            ull z2 = p2_fma(p2_fma(u2p[nt], r2p, nm2p), g2p, be2p);
            p2_unpack(z2, za, zb);
            d2p = p2_fma(p2_pack(fmaxf(za, 0.f), fmaxf(zb, 0.f)), w3p, d2p);
        }
        p2_unpack(d1p, lo, hi); float d1 = qred(lo + hi);
        p2_unpack(d2p, lo, hi); float d2 = qred(lo + hi);
        if (qc == 0) {
            out[i * NN + j1]     = 1.f / (1.f + __expf(-(d1 + s_b3)));
            out[i * NN + j1 + 8] = 1.f / (1.f + __expf(-(d2 + s_b3)));
        }
    }
}

// ---------------- launch ----------------
extern "C" void kernel_launch(void* const* d_in, const int* in_sizes, int n_in,
                              void* d_out, int out_size) {
    const float* X   = (const float*)d_in[0];
    const float* W1  = (const float*)d_in[1];
    const float* b1  = (const float*)d_in[2];
    const float* g1  = (const float*)d_in[3];
    const float* be1 = (const float*)d_in[4];
    const float* W2  = (const float*)d_in[5];
    const float* b2  = (const float*)d_in[6];
    const float* g2  = (const float*)d_in[7];
    const float* be2 = (const float*)d_in[8];
    const float* W3  = (const float*)d_in[9];
    const float* b3  = (const float*)d_in[10];
    float* out = (float*)d_out;

    prep_all<<<260, 256>>>(X, W1, b1, W2);
    dim3 grid(NN / 16, NN / 8);
    pair_kernel<<<grid, 128>>>(g1, be1, b2, g2, be2, W3, b3, out);
}